// round 7
// baseline (speedup 1.0000x reference)
#include <cuda_runtime.h>
#include <cuda_bf16.h>

// ROI bilinear pooling (tf.image.resize half-pixel-center semantics, per ROI).
// img:  (1, 64, 64, 1024) float32, NHWC
// rois: (1, R, 4) int32  [x, y, w, h]
// out:  (1, R, 7, 7, 1024) float32
//
// R6: one CTA per ROI. 256 threads x float4 channel slice. X-axis coordinate
// tables computed once per ROI (CTA-uniform), then a rolled row loop with an
// unrolled branch-free 7-pixel body (4 independent LDG.128 per pixel, full MLP,
// same load structure as the winning R3 kernel). Grid = 1024 -> single wave.

#define POOL 7
#define HW   64
#define C    1024
#define C4   (C / 4)

__global__ __launch_bounds__(256, 7) void roi_pool_roi_kernel(
    const float* __restrict__ img,
    const int*   __restrict__ rois,
    float*       __restrict__ out)
{
    const int r = blockIdx.x;

    // ROI box [x, y, w, h] (broadcast load)
    const int4 roi = __ldg(((const int4*)rois) + r);
    const int bx = roi.x, by = roi.y, bw = roi.z, bh = roi.w;

    // ---- horizontal coordinate tables: ONCE per ROI (CTA-uniform) ----
    const float xscale = (float)bw / (float)POOL;
    const int   xmax   = bw - 1;
    int   xo0[POOL], xo1[POOL];
    float txs[POOL];
#pragma unroll
    for (int px = 0; px < POOL; px++) {
        const float sx = (px + 0.5f) * xscale - 0.5f;
        const float fx = floorf(sx);
        txs[px] = sx - fx;
        const int ix = (int)fx;
        xo0[px] = (bx + min(max(ix,     0), xmax)) * C4;
        xo1[px] = (bx + min(max(ix + 1, 0), xmax)) * C4;
    }

    const int c = threadIdx.x;                       // channel slice 0..255
    const float4* imgc = ((const float4*)img) + c;
    float4* outr = ((float4*)out) + (size_t)r * (POOL * POOL * C4) + c;

    const float yscale = (float)bh / (float)POOL;
    const int   ymax   = bh - 1;

#pragma unroll 1
    for (int py = 0; py < POOL; py++) {
        // ---- vertical coords for this row ----
        const float sy = (py + 0.5f) * yscale - 0.5f;
        const float fy = floorf(sy);
        const float ty = sy - fy;
        const int   iy = (int)fy;
        const int   y0 = by + min(max(iy,     0), ymax);
        const int   y1 = by + min(max(iy + 1, 0), ymax);
        const float wty0 = 1.0f - ty;

        const float4* r0 = imgc + y0 * (HW * C4);
        const float4* r1 = imgc + y1 * (HW * C4);
        float4* orow = outr + py * (POOL * C4);

#pragma unroll
        for (int px = 0; px < POOL; px++) {
            const float tx   = txs[px];
            const float wtx0 = 1.0f - tx;

            const float4 a = __ldg(r0 + xo0[px]);
            const float4 b = __ldg(r0 + xo1[px]);
            const float4 g = __ldg(r1 + xo0[px]);
            const float4 d = __ldg(r1 + xo1[px]);

            float4 o;
            {
                float top = a.x * wtx0 + b.x * tx;
                float bot = g.x * wtx0 + d.x * tx;
                o.x = top * wty0 + bot * ty;
            }
            {
                float top = a.y * wtx0 + b.y * tx;
                float bot = g.y * wtx0 + d.y * tx;
                o.y = top * wty0 + bot * ty;
            }
            {
                float top = a.z * wtx0 + b.z * tx;
                float bot = g.z * wtx0 + d.z * tx;
                o.z = top * wty0 + bot * ty;
            }
            {
                float top = a.w * wtx0 + b.w * tx;
                float bot = g.w * wtx0 + d.w * tx;
                o.w = top * wty0 + bot * ty;
            }

            orow[px * C4] = o;
        }
    }
}

extern "C" void kernel_launch(void* const* d_in, const int* in_sizes, int n_in,
                              void* d_out, int out_size)
{
    const float* img  = (const float*)d_in[0];
    const int*   rois = (const int*)d_in[1];
    float*       out  = (float*)d_out;

    const int R = in_sizes[1] / 4;       // number of ROIs
    roi_pool_roi_kernel<<<R, 256>>>(img, rois, out);
}

// round 11
// speedup vs baseline: 1.3156x; 1.3156x over previous
#include <cuda_runtime.h>
#include <cuda_bf16.h>

// ROI bilinear pooling (tf.image.resize half-pixel-center semantics, per ROI).
// img:  (1, 64, 64, 1024) float32, NHWC
// rois: (1, R, 4) int32  [x, y, w, h]
// out:  (1, R, 7, 7, 1024) float32
//
// R7: one CTA per ROI (grid=1024 -> ~single wave, no wave-transition cost).
// 256 threads x float4 channel slice. BOTH pool loops fully unrolled: 49
// inline pixel sites, coordinate math inline (no indexed arrays -> no local
// spills), branch-free 4-load bilinear body identical to the winning R3 shape.

#define POOL 7
#define HW   64
#define C    1024
#define C4   (C / 4)

__global__ __launch_bounds__(256, 6) void roi_pool_roi_kernel(
    const float* __restrict__ img,
    const int*   __restrict__ rois,
    float*       __restrict__ out)
{
    const int r = blockIdx.x;

    // ROI box [x, y, w, h] (broadcast load)
    const int4 roi = __ldg(((const int4*)rois) + r);
    const int bx = roi.x, by = roi.y, bw = roi.z, bh = roi.w;

    const float xscale = (float)bw / (float)POOL;
    const float yscale = (float)bh / (float)POOL;
    const int   xmax   = bw - 1;
    const int   ymax   = bh - 1;

    const int c = threadIdx.x;                       // channel slice 0..255
    const float4* imgc = ((const float4*)img) + c;
    float4* outr = ((float4*)out) + (size_t)r * (POOL * POOL * C4) + c;

#pragma unroll
    for (int py = 0; py < POOL; py++) {
        // ---- vertical coords (inline per unrolled site) ----
        const float sy = (py + 0.5f) * yscale - 0.5f;
        const float fy = floorf(sy);
        const float ty = sy - fy;
        const int   iy = (int)fy;
        const int   y0 = by + min(max(iy,     0), ymax);
        const int   y1 = by + min(max(iy + 1, 0), ymax);
        const float wty0 = 1.0f - ty;

        const float4* r0 = imgc + y0 * (HW * C4);
        const float4* r1 = imgc + y1 * (HW * C4);
        float4* orow = outr + py * (POOL * C4);

#pragma unroll
        for (int px = 0; px < POOL; px++) {
            // ---- horizontal coords (inline per unrolled site) ----
            const float sx = (px + 0.5f) * xscale - 0.5f;
            const float fx = floorf(sx);
            const float tx = sx - fx;
            const int   ix = (int)fx;
            const int   x0 = bx + min(max(ix,     0), xmax);
            const int   x1 = bx + min(max(ix + 1, 0), xmax);
            const float wtx0 = 1.0f - tx;

            const float4 a = __ldg(r0 + x0 * C4);
            const float4 b = __ldg(r0 + x1 * C4);
            const float4 g = __ldg(r1 + x0 * C4);
            const float4 d = __ldg(r1 + x1 * C4);

            float4 o;
            {
                float top = a.x * wtx0 + b.x * tx;
                float bot = g.x * wtx0 + d.x * tx;
                o.x = top * wty0 + bot * ty;
            }
            {
                float top = a.y * wtx0 + b.y * tx;
                float bot = g.y * wtx0 + d.y * tx;
                o.y = top * wty0 + bot * ty;
            }
            {
                float top = a.z * wtx0 + b.z * tx;
                float bot = g.z * wtx0 + d.z * tx;
                o.z = top * wty0 + bot * ty;
            }
            {
                float top = a.w * wtx0 + b.w * tx;
                float bot = g.w * wtx0 + d.w * tx;
                o.w = top * wty0 + bot * ty;
            }

            orow[px * C4] = o;
        }
    }
}

extern "C" void kernel_launch(void* const* d_in, const int* in_sizes, int n_in,
                              void* d_out, int out_size)
{
    const float* img  = (const float*)d_in[0];
    const int*   rois = (const int*)d_in[1];
    float*       out  = (float*)d_out;

    const int R = in_sizes[1] / 4;       // number of ROIs
    roi_pool_roi_kernel<<<R, 256>>>(img, rois, out);
}